// round 8
// baseline (speedup 1.0000x reference)
#include <cuda_runtime.h>
#include <cuda_fp16.h>
#include <math.h>
#include <stdint.h>

#define B_   2
#define T_   4096
#define D_   512
#define H_   8
#define HD_  64
#define W_   32
#define HID_ 1536
#define NTOK (B_*T_)

// ---------------- scratch (device globals; no allocs allowed) ----------------
__device__ float g_h  [(size_t)NTOK * D_];
__device__ float g_tmp[(size_t)NTOK * D_];
__device__ float g_y  [(size_t)NTOK * D_];
__device__ float g_z  [(size_t)NTOK * D_];
__device__ __half g_qkvh[(size_t)NTOK * 3 * D_];     // fp16 qkv
__device__ __half g_a2[(size_t)NTOK * D_];           // fp16 activations (K=512 GEMM A)
__device__ __half g_a3[(size_t)NTOK * HID_];         // fp16 silu output (K=1536 GEMM A)
__device__ __half g_b2[(size_t)3355443];             // fp16 B^T

// ======================= PTX helpers (baseline ISA only) =======================
__device__ __forceinline__ uint32_t s2u(const void* p) {
  uint32_t a;
  asm("{ .reg .u64 t; cvta.to.shared.u64 t, %1; cvt.u32.u64 %0, t; }" : "=r"(a) : "l"(p));
  return a;
}
__device__ __forceinline__ void cp16(uint32_t dst, const void* src) {
  asm volatile("cp.async.cg.shared.global [%0], [%1], 16;" :: "r"(dst), "l"(src) : "memory");
}
__device__ __forceinline__ void cp_commit() { asm volatile("cp.async.commit_group;" ::: "memory"); }
template<int N>
__device__ __forceinline__ void cp_wait() { asm volatile("cp.async.wait_group %0;" :: "n"(N) : "memory"); }

__device__ __forceinline__ void ldsm4(uint32_t* r, uint32_t addr) {
  asm volatile("ldmatrix.sync.aligned.m8n8.x4.shared.b16 {%0,%1,%2,%3}, [%4];"
               : "=r"(r[0]), "=r"(r[1]), "=r"(r[2]), "=r"(r[3]) : "r"(addr));
}
__device__ __forceinline__ void mma16816(float* d, const uint32_t* a, const uint32_t* b) {
  asm volatile(
      "mma.sync.aligned.m16n8k16.row.col.f32.f16.f16.f32 "
      "{%0,%1,%2,%3}, {%4,%5,%6,%7}, {%8,%9}, {%0,%1,%2,%3};"
      : "+f"(d[0]), "+f"(d[1]), "+f"(d[2]), "+f"(d[3])
      : "r"(a[0]), "r"(a[1]), "r"(a[2]), "r"(a[3]), "r"(b[0]), "r"(b[1]));
}

__device__ __forceinline__ uint2 pack4h(const float4& v) {
  union { __half b[4]; uint2 u; } hu;
  hu.b[0] = __float2half_rn(v.x); hu.b[1] = __float2half_rn(v.y);
  hu.b[2] = __float2half_rn(v.z); hu.b[3] = __float2half_rn(v.w);
  return hu.u;
}

// ======================= weight transpose to fp16: w[K,N] -> out[n][K] ======
__global__ void split_bt_kernel(const float* __restrict__ w,
                                __half* __restrict__ out, int K, int N) {
  __shared__ float t[32][33];
  int n0 = blockIdx.x * 32, k0 = blockIdx.y * 32;
  t[threadIdx.y][threadIdx.x] = w[(size_t)(k0 + threadIdx.y) * N + n0 + threadIdx.x];
  __syncthreads();
  int n = n0 + threadIdx.y, k = k0 + threadIdx.x;
  out[(size_t)n * K + k] = __float2half_rn(t[threadIdx.x][threadIdx.y]);
}

// interleaved variant for gate/val: logical col j -> B2 row (j/8)*16 + j%8 + off
__global__ void split_bt_ilv_kernel(const float* __restrict__ w,
                                    __half* __restrict__ out, int K, int N, int off) {
  __shared__ float t[32][33];
  int n0 = blockIdx.x * 32, k0 = blockIdx.y * 32;
  t[threadIdx.y][threadIdx.x] = w[(size_t)(k0 + threadIdx.y) * N + n0 + threadIdx.x];
  __syncthreads();
  int j = n0 + threadIdx.y, k = k0 + threadIdx.x;
  int r = ((j >> 3) << 4) + (j & 7) + off;
  out[(size_t)r * K + k] = __float2half_rn(t[threadIdx.x][threadIdx.y]);
}

// ======================= mma.sync fp16 GEMM =======================
// C[M,N] = A2[M,K] @ B2[N,K]^T. CTA tile 128x128, BK=64, 2-stage double buffer.
// 128 threads / 4 warps, warp tile 64x64 (HMMA:ldsm = 4:1).
// MODE 0: fp32 C.  MODE 1: silu(gate)*val -> half OUT[M,N/2] (interleaved B).
// MODE 2: half OUT[M,N].
#define STAGE_BYTES 32768          /* A 16KB + B 16KB */
#define GEMM_DYN_SMEM (2*STAGE_BYTES + 1024)

template<int MODE>
__global__ __launch_bounds__(128, 2) void gemm_mma(
    const __half* __restrict__ A2, const __half* __restrict__ B2,
    float* __restrict__ C, __half* __restrict__ OUT, int N, int K) {
  extern __shared__ char smraw[];
  uint32_t sb0 = s2u(smraw);
  const uint32_t sb = sb0 + ((1024u - (sb0 & 1023u)) & 1023u);

  const int tid = threadIdx.x, lane = tid & 31, wid = tid >> 5;
  const int bm = blockIdx.y * 128, bn = blockIdx.x * 128;
  const int wm = (wid >> 1) * 64, wn = (wid & 1) * 64;

  float acc[4][8][4];
#pragma unroll
  for (int mt = 0; mt < 4; mt++)
#pragma unroll
    for (int nt = 0; nt < 8; nt++)
#pragma unroll
      for (int e = 0; e < 4; e++) acc[mt][nt][e] = 0.f;

  const int arow = wm + (lane & 15);
  const int ach  = lane >> 4;
  const int brow = wn + (lane & 7) + ((lane >> 1) & 8);
  const int bch  = (lane >> 3) & 1;

  const int nIter = K >> 6;

  auto loadStage = [&](int i) {
    uint32_t st = sb + (uint32_t)(i & 1) * STAGE_BYTES;
    size_t koff = (size_t)i * 128;    // 64 halves = 128 B
#pragma unroll
    for (int j = 0; j < 8; j++) {
      int s = tid + j * 128, r = s >> 3, c = s & 7;
      uint32_t off = (uint32_t)(r * 128 + ((c ^ (r & 7)) << 4));
      cp16(st + off,          (const char*)(A2 + (size_t)(bm + r) * K) + c * 16 + koff);
      cp16(st + 16384 + off,  (const char*)(B2 + (size_t)(bn + r) * K) + c * 16 + koff);
    }
    cp_commit();
  };

  loadStage(0);

  for (int i = 0; i < nIter; i++) {
    cp_wait<0>();
    __syncthreads();
    if (i + 1 < nIter) loadStage(i + 1);

    const uint32_t sa  = sb + (uint32_t)(i & 1) * STAGE_BYTES;
    const uint32_t sbB = sa + 16384;
#pragma unroll
    for (int ks = 0; ks < 4; ks++) {
      uint32_t afr[4][4];
#pragma unroll
      for (int mt = 0; mt < 4; mt++) {
        int row = arow + mt * 16;
        int ch  = 2 * ks + ach;
        ldsm4(afr[mt], sa + row * 128 + (((uint32_t)(ch ^ (row & 7))) << 4));
      }
      uint32_t bfr[4][4];
#pragma unroll
      for (int nt = 0; nt < 4; nt++) {
        int row = brow + nt * 16;
        int ch  = 2 * ks + bch;
        ldsm4(bfr[nt], sbB + row * 128 + (((uint32_t)(ch ^ (row & 7))) << 4));
      }
#pragma unroll
      for (int mt = 0; mt < 4; mt++)
#pragma unroll
        for (int n8 = 0; n8 < 8; n8++)
          mma16816(acc[mt][n8], afr[mt], &bfr[n8 >> 1][(n8 & 1) * 2]);
    }
  }

  const int crow = lane >> 2;
  const int ccol = (lane & 3) * 2;
  if (MODE == 1) {
    // cols 16b+c: c<8 -> gate_j, c>=8 -> val_j, j = 8b+c. n8 even gate, odd val.
    const int stride = N >> 1;
#pragma unroll
    for (int mt = 0; mt < 4; mt++) {
#pragma unroll
      for (int t = 0; t < 4; t++) {
        const float* gp = acc[mt][2*t];
        const float* vp = acc[mt][2*t+1];
        int j0   = ((bn + wn) >> 1) + 8*t + ccol;
        int row0 = bm + wm + mt*16 + crow;
        float o0 = gp[0] / (1.f + __expf(-gp[0])) * vp[0];
        float o1 = gp[1] / (1.f + __expf(-gp[1])) * vp[1];
        *(__half2*)&OUT[(size_t)row0 * stride + j0] = __floats2half2_rn(o0, o1);
        float o2 = gp[2] / (1.f + __expf(-gp[2])) * vp[2];
        float o3 = gp[3] / (1.f + __expf(-gp[3])) * vp[3];
        *(__half2*)&OUT[(size_t)(row0 + 8) * stride + j0] = __floats2half2_rn(o2, o3);
      }
    }
  } else if (MODE == 2) {
#pragma unroll
    for (int mt = 0; mt < 4; mt++) {
#pragma unroll
      for (int n8 = 0; n8 < 8; n8++) {
        int col  = bn + wn + n8 * 8 + ccol;
        int row0 = bm + wm + mt * 16 + crow;
        const float* ap = acc[mt][n8];
        *(__half2*)&OUT[(size_t)row0 * N + col]       = __floats2half2_rn(ap[0], ap[1]);
        *(__half2*)&OUT[(size_t)(row0 + 8) * N + col] = __floats2half2_rn(ap[2], ap[3]);
      }
    }
  } else {
#pragma unroll
    for (int mt = 0; mt < 4; mt++) {
#pragma unroll
      for (int n8 = 0; n8 < 8; n8++) {
        size_t r0 = (size_t)(bm + wm + mt * 16 + crow) * N + (bn + wn + n8 * 8 + ccol);
        *(float2*)&C[r0]                 = make_float2(acc[mt][n8][0], acc[mt][n8][1]);
        *(float2*)&C[r0 + (size_t)8 * N] = make_float2(acc[mt][n8][2], acc[mt][n8][3]);
      }
    }
  }
}

// ======================= windowed sigmoid attention =======================
// reads fp16 qkv [tok][1536]; writes fp16 msg into a2[tok][512].
#define AT_TOKS (128 + W_)
#define AT_PAD  161

__global__ __launch_bounds__(128) void attn_kernel(
    const __half* __restrict__ qkv, __half* __restrict__ a2) {
  extern __shared__ float smf[];
  float* ks = smf;
  float* vs = smf + 64 * AT_PAD;
  const int c = blockIdx.x, h = blockIdx.y, b = blockIdx.z;
  const int base = c * 128 - W_;
  const int tid = threadIdx.x;

  for (int i4 = tid; i4 < AT_TOKS * 32; i4 += 128) {
    int tok = i4 >> 5;
    int dq  = (i4 & 31) << 2;
    int tg  = base + tok;
    float4 v = make_float4(0.f, 0.f, 0.f, 0.f);
    if (tg >= 0) {
      uint2 raw = *(const uint2*)&qkv[(size_t)(b*T_ + tg)*(3*D_) + D_ + h*128 + dq];
      float2 f0 = __half22float2(*(__half2*)&raw.x);
      float2 f1 = __half22float2(*(__half2*)&raw.y);
      v = make_float4(f0.x, f0.y, f1.x, f1.y);
    }
    float* dst = (dq < 64) ? (ks + dq*AT_PAD + tok) : (vs + (dq-64)*AT_PAD + tok);
    dst[0]        = v.x;
    dst[AT_PAD]   = v.y;
    dst[2*AT_PAD] = v.z;
    dst[3*AT_PAD] = v.w;
  }
  __syncthreads();

  const int tg = c * 128 + tid;
  const __half* qp = &qkv[(size_t)(b*T_ + tg)*(3*D_) + h*HD_];
  float qr[64];
#pragma unroll
  for (int i = 0; i < 16; i++) {
    uint2 raw = *(const uint2*)(qp + 4*i);
    float2 f0 = __half22float2(*(__half2*)&raw.x);
    float2 f1 = __half22float2(*(__half2*)&raw.y);
    qr[4*i]=f0.x; qr[4*i+1]=f0.y; qr[4*i+2]=f1.x; qr[4*i+3]=f1.y;
  }
  float acc[64];
#pragma unroll
  for (int d = 0; d < 64; d++) acc[d] = 0.f;

  const int jt = tid + W_;
#pragma unroll 4
  for (int w = 0; w < W_; w += 2) {
    const int j0 = jt - 1 - w;
    const int j1 = jt - 2 - w;
    float s0=0.f, s1=0.f, s2=0.f, s3=0.f;
    float u0=0.f, u1=0.f, u2=0.f, u3=0.f;
#pragma unroll
    for (int d = 0; d < 64; d += 4) {
      s0 += qr[d]   * ks[(d)  *AT_PAD + j0];
      s1 += qr[d+1] * ks[(d+1)*AT_PAD + j0];
      s2 += qr[d+2] * ks[(d+2)*AT_PAD + j0];
      s3 += qr[d+3] * ks[(d+3)*AT_PAD + j0];
      u0 += qr[d]   * ks[(d)  *AT_PAD + j1];
      u1 += qr[d+1] * ks[(d+1)*AT_PAD + j1];
      u2 += qr[d+2] * ks[(d+2)*AT_PAD + j1];
      u3 += qr[d+3] * ks[(d+3)*AT_PAD + j1];
    }
    float sA = (s0+s1) + (s2+s3);
    float sB = (u0+u1) + (u2+u3);
    float tau0 = 1.f / (1.f + __expf(-sA * 0.125f));
    float tau1 = 1.f / (1.f + __expf(-sB * 0.125f));
#pragma unroll
    for (int d = 0; d < 64; d++)
      acc[d] += tau0 * vs[d*AT_PAD + j0] + tau1 * vs[d*AT_PAD + j1];
  }

  size_t abase = (size_t)(b*T_ + tg) * D_;
  int off = h * HD_;
#pragma unroll
  for (int i = 0; i < 16; i++) {
    float4 v = make_float4(acc[4*i], acc[4*i+1], acc[4*i+2], acc[4*i+3]);
    *(uint2*)(a2 + abase + off + 4*i) = pack4h(v);
  }
}

// ======================= LayerNorm (+residual, +mod, +fp16 out) =======================
template<int MODE, int SPLIT>
__global__ __launch_bounds__(128) void ln_kernel(
    const float* __restrict__ x, const float* __restrict__ add,
    const float* __restrict__ g, const float* __restrict__ bb,
    const float* __restrict__ freqs, const float* __restrict__ phases,
    const float* __restrict__ amp, float* __restrict__ out,
    __half* __restrict__ a2) {
  const int row = blockIdx.x;
  const int i = threadIdx.x;
  float4 f = ((const float4*)(x + (size_t)row*D_))[i];
  if (MODE >= 1) {
    float4 a = ((const float4*)(add + (size_t)row*D_))[i];
    f.x+=a.x; f.y+=a.y; f.z+=a.z; f.w+=a.w;
  }
  float s  = f.x + f.y + f.z + f.w;
  float ss = f.x*f.x + f.y*f.y + f.z*f.z + f.w*f.w;
#pragma unroll
  for (int o = 16; o > 0; o >>= 1) {
    s  += __shfl_xor_sync(0xffffffffu, s,  o);
    ss += __shfl_xor_sync(0xffffffffu, ss, o);
  }
  __shared__ float rs[4], rss[4];
  if ((i & 31) == 0) { rs[i>>5] = s; rss[i>>5] = ss; }
  __syncthreads();
  s  = rs[0]  + rs[1]  + rs[2]  + rs[3];
  ss = rss[0] + rss[1] + rss[2] + rss[3];
  const float mu   = s * (1.f/D_);
  const float var  = ss * (1.f/D_) - mu*mu;
  const float rstd = rsqrtf(var + 1e-5f);
  float4 gv = ((const float4*)g)[i];
  float4 bv = ((const float4*)bb)[i];
  float4 o;
  o.x = (f.x-mu)*rstd*gv.x + bv.x;
  o.y = (f.y-mu)*rstd*gv.y + bv.y;
  o.z = (f.z-mu)*rstd*gv.z + bv.z;
  o.w = (f.w-mu)*rstd*gv.w + bv.w;
  if (MODE == 1) {
    float t  = (float)(row & (T_-1));
    float av = amp[0];
    float4 fr = ((const float4*)freqs)[i];
    float4 ph = ((const float4*)phases)[i];
    o.x *= 1.f + av*sinf(t*fr.x + ph.x);
    o.y *= 1.f + av*sinf(t*fr.y + ph.y);
    o.z *= 1.f + av*sinf(t*fr.z + ph.z);
    o.w *= 1.f + av*sinf(t*fr.w + ph.w);
  }
  ((float4*)(out + (size_t)row*D_))[i] = o;
  if (SPLIT) {
    *(uint2*)(a2 + (size_t)row * D_ + i * 4) = pack4h(o);
  }
}

// ======================= launch =======================
extern "C" void kernel_launch(void* const* d_in, const int* in_sizes, int n_in,
                              void* d_out, int out_size) {
  const float* x      = (const float*)d_in[0];
  const float* pre_g  = (const float*)d_in[1];
  const float* pre_b  = (const float*)d_in[2];
  const float* wq     = (const float*)d_in[3];
  const float* wkv    = (const float*)d_in[4];
  const float* wo     = (const float*)d_in[5];
  const float* attn_g = (const float*)d_in[6];
  const float* attn_b = (const float*)d_in[7];
  const float* freqs  = (const float*)d_in[8];
  const float* phases = (const float*)d_in[9];
  const float* amp    = (const float*)d_in[10];
  const float* w_gate = (const float*)d_in[11];
  const float* w_val  = (const float*)d_in[12];
  const float* w_proj = (const float*)d_in[13];
  const float* ffn_g  = (const float*)d_in[14];
  const float* ffn_b  = (const float*)d_in[15];

  float *h, *tmp, *y, *z;
  __half *qkvh, *a2, *a3, *b2;
  cudaGetSymbolAddress((void**)&h,    g_h);
  cudaGetSymbolAddress((void**)&tmp,  g_tmp);
  cudaGetSymbolAddress((void**)&y,    g_y);
  cudaGetSymbolAddress((void**)&z,    g_z);
  cudaGetSymbolAddress((void**)&qkvh, g_qkvh);
  cudaGetSymbolAddress((void**)&a2,   g_a2);
  cudaGetSymbolAddress((void**)&a3,   g_a3);
  cudaGetSymbolAddress((void**)&b2,   g_b2);

  const int ATTN_SMEM = 2 * 64 * AT_PAD * sizeof(float);
  cudaFuncSetAttribute(attn_kernel, cudaFuncAttributeMaxDynamicSharedMemorySize, ATTN_SMEM);
  cudaFuncSetAttribute(gemm_mma<0>, cudaFuncAttributeMaxDynamicSharedMemorySize, GEMM_DYN_SMEM);
  cudaFuncSetAttribute(gemm_mma<1>, cudaFuncAttributeMaxDynamicSharedMemorySize, GEMM_DYN_SMEM);
  cudaFuncSetAttribute(gemm_mma<2>, cudaFuncAttributeMaxDynamicSharedMemorySize, GEMM_DYN_SMEM);

  // 1) h = LN(x) (+ fp16 copy into a2, K=512)
  ln_kernel<0,1><<<NTOK, 128>>>(x, nullptr, pre_g, pre_b, nullptr, nullptr, nullptr, h, a2);

  // 2) qkv = h @ [wq | wkv], N=1536, K=512, fp16 output
  split_bt_kernel<<<dim3(D_/32,   D_/32), dim3(32,32)>>>(wq,  b2,                    D_, D_);
  split_bt_kernel<<<dim3(2*D_/32, D_/32), dim3(32,32)>>>(wkv, b2 + (size_t)D_ * D_,  D_, 2*D_);
  gemm_mma<2><<<dim3(12, 64), 128, GEMM_DYN_SMEM>>>(a2, b2, nullptr, qkvh, 3*D_, D_);

  // 3) attention -> fp16 msg into a2
  attn_kernel<<<dim3(T_/128, H_, B_), 128, ATTN_SMEM>>>(qkvh, a2);

  // 4) tmp = msg@wo ; y = LN(h+tmp)*(1+amp*sin) (+ fp16 into a2)
  split_bt_kernel<<<dim3(D_/32, D_/32), dim3(32,32)>>>(wo, b2, D_, D_);
  gemm_mma<0><<<dim3(4, 64), 128, GEMM_DYN_SMEM>>>(a2, b2, tmp, nullptr, D_, D_);
  ln_kernel<1,1><<<NTOK, 128>>>(h, tmp, attn_g, attn_b, freqs, phases, amp, y, a2);

  // 5) FFN: fused gv GEMM (gate/val interleaved, silu epilogue -> a3 fp16)
  split_bt_ilv_kernel<<<dim3(HID_/32, D_/32), dim3(32,32)>>>(w_gate, b2, D_, HID_, 0);
  split_bt_ilv_kernel<<<dim3(HID_/32, D_/32), dim3(32,32)>>>(w_val,  b2, D_, HID_, 8);
  gemm_mma<1><<<dim3(24, 64), 128, GEMM_DYN_SMEM>>>(a2, b2, nullptr, a3, 2*HID_, D_);

  // z = a3 @ w_proj, N=512, K=1536
  split_bt_kernel<<<dim3(D_/32, HID_/32), dim3(32,32)>>>(w_proj, b2, HID_, D_);
  gemm_mma<0><<<dim3(4, 64), 128, GEMM_DYN_SMEM>>>(a3, b2, z, nullptr, D_, HID_);

  // 6) out = LN(y + z)
  ln_kernel<2,0><<<NTOK, 128>>>(y, z, ffn_g, ffn_b, nullptr, nullptr, nullptr, (float*)d_out, nullptr);
}

// round 9
// speedup vs baseline: 1.0016x; 1.0016x over previous
#include <cuda_runtime.h>
#include <cuda_fp16.h>
#include <math.h>
#include <stdint.h>

#define B_   2
#define T_   4096
#define D_   512
#define H_   8
#define HD_  64
#define W_   32
#define HID_ 1536
#define NTOK (B_*T_)

// ---------------- scratch (device globals; no allocs allowed) ----------------
__device__ float g_h  [(size_t)NTOK * D_];
__device__ float g_tmp[(size_t)NTOK * D_];
__device__ float g_y  [(size_t)NTOK * D_];
__device__ float g_z  [(size_t)NTOK * D_];
__device__ __half g_qkvh[(size_t)NTOK * 3 * D_];     // fp16 qkv
__device__ __half g_a2[(size_t)NTOK * D_];           // fp16 activations (K=512 GEMM A)
__device__ __half g_a3[(size_t)NTOK * HID_];         // fp16 silu output (K=1536 GEMM A)
__device__ __half g_b2[(size_t)3355443];             // fp16 B^T

// ======================= PTX helpers (baseline ISA only) =======================
__device__ __forceinline__ uint32_t s2u(const void* p) {
  uint32_t a;
  asm("{ .reg .u64 t; cvta.to.shared.u64 t, %1; cvt.u32.u64 %0, t; }" : "=r"(a) : "l"(p));
  return a;
}
__device__ __forceinline__ void cp16(uint32_t dst, const void* src) {
  asm volatile("cp.async.cg.shared.global [%0], [%1], 16;" :: "r"(dst), "l"(src) : "memory");
}
__device__ __forceinline__ void cp_commit() { asm volatile("cp.async.commit_group;" ::: "memory"); }
template<int N>
__device__ __forceinline__ void cp_wait() { asm volatile("cp.async.wait_group %0;" :: "n"(N) : "memory"); }

__device__ __forceinline__ void ldsm4(uint32_t* r, uint32_t addr) {
  asm volatile("ldmatrix.sync.aligned.m8n8.x4.shared.b16 {%0,%1,%2,%3}, [%4];"
               : "=r"(r[0]), "=r"(r[1]), "=r"(r[2]), "=r"(r[3]) : "r"(addr));
}
__device__ __forceinline__ void mma16816(float* d, const uint32_t* a, const uint32_t* b) {
  asm volatile(
      "mma.sync.aligned.m16n8k16.row.col.f32.f16.f16.f32 "
      "{%0,%1,%2,%3}, {%4,%5,%6,%7}, {%8,%9}, {%0,%1,%2,%3};"
      : "+f"(d[0]), "+f"(d[1]), "+f"(d[2]), "+f"(d[3])
      : "r"(a[0]), "r"(a[1]), "r"(a[2]), "r"(a[3]), "r"(b[0]), "r"(b[1]));
}

__device__ __forceinline__ uint2 pack4h(const float4& v) {
  union { __half b[4]; uint2 u; } hu;
  hu.b[0] = __float2half_rn(v.x); hu.b[1] = __float2half_rn(v.y);
  hu.b[2] = __float2half_rn(v.z); hu.b[3] = __float2half_rn(v.w);
  return hu.u;
}

// ======================= weight transpose to fp16: w[K,N] -> out[n][K] ======
__global__ void split_bt_kernel(const float* __restrict__ w,
                                __half* __restrict__ out, int K, int N) {
  __shared__ float t[32][33];
  int n0 = blockIdx.x * 32, k0 = blockIdx.y * 32;
  t[threadIdx.y][threadIdx.x] = w[(size_t)(k0 + threadIdx.y) * N + n0 + threadIdx.x];
  __syncthreads();
  int n = n0 + threadIdx.y, k = k0 + threadIdx.x;
  out[(size_t)n * K + k] = __float2half_rn(t[threadIdx.x][threadIdx.y]);
}

// interleaved variant for gate/val: logical col j -> B2 row (j/8)*16 + j%8 + off
__global__ void split_bt_ilv_kernel(const float* __restrict__ w,
                                    __half* __restrict__ out, int K, int N, int off) {
  __shared__ float t[32][33];
  int n0 = blockIdx.x * 32, k0 = blockIdx.y * 32;
  t[threadIdx.y][threadIdx.x] = w[(size_t)(k0 + threadIdx.y) * N + n0 + threadIdx.x];
  __syncthreads();
  int j = n0 + threadIdx.y, k = k0 + threadIdx.x;
  int r = ((j >> 3) << 4) + (j & 7) + off;
  out[(size_t)r * K + k] = __float2half_rn(t[threadIdx.x][threadIdx.y]);
}

// ======================= mma.sync fp16 GEMM (R7-proven config) =======================
// C[M,N] = A2[M,K] @ B2[N,K]^T. CTA tile 128x128, BK=64, 2-stage double buffer,
// 256 threads / 8 warps, warp tile 32x64.
// MODE 0: fp32 C.  MODE 1: silu(gate)*val -> half OUT[M,N/2] (interleaved B).
// MODE 2: half OUT[M,N].
#define STAGE_BYTES 32768          /* A 16KB + B 16KB */
#define GEMM_DYN_SMEM (2*STAGE_BYTES + 1024)

template<int MODE>
__global__ __launch_bounds__(256, 2) void gemm_mma(
    const __half* __restrict__ A2, const __half* __restrict__ B2,
    float* __restrict__ C, __half* __restrict__ OUT, int N, int K) {
  extern __shared__ char smraw[];
  uint32_t sb0 = s2u(smraw);
  const uint32_t sb = sb0 + ((1024u - (sb0 & 1023u)) & 1023u);

  const int tid = threadIdx.x, lane = tid & 31, wid = tid >> 5;
  const int bm = blockIdx.y * 128, bn = blockIdx.x * 128;
  const int wm = (wid >> 1) * 32, wn = (wid & 1) * 64;

  uint32_t aOff[4], bOff[4];
  const char *aSrc[4], *bSrc[4];
#pragma unroll
  for (int j = 0; j < 4; j++) {
    int s = tid + j * 256, r = s >> 3, c = s & 7;
    uint32_t off = (uint32_t)(r * 128 + ((c ^ (r & 7)) << 4));
    aOff[j] = off;
    bOff[j] = off;
    aSrc[j] = (const char*)(A2 + (size_t)(bm + r) * K) + c * 16;
    bSrc[j] = (const char*)(B2 + (size_t)(bn + r) * K) + c * 16;
  }

  float acc[2][8][4];
#pragma unroll
  for (int mt = 0; mt < 2; mt++)
#pragma unroll
    for (int nt = 0; nt < 8; nt++)
#pragma unroll
      for (int e = 0; e < 4; e++) acc[mt][nt][e] = 0.f;

  const int arow = wm + (lane & 15);
  const int ach  = lane >> 4;
  const int brow = wn + (lane & 7) + ((lane >> 1) & 8);
  const int bch  = (lane >> 3) & 1;

  const int nIter = K >> 6;

  auto loadStage = [&](int i) {
    uint32_t st = sb + (uint32_t)(i & 1) * STAGE_BYTES;
    size_t koff = (size_t)i * 128;
#pragma unroll
    for (int j = 0; j < 4; j++) cp16(st + aOff[j], aSrc[j] + koff);
#pragma unroll
    for (int j = 0; j < 4; j++) cp16(st + 16384 + bOff[j], bSrc[j] + koff);
    cp_commit();
  };

  loadStage(0);

  for (int i = 0; i < nIter; i++) {
    cp_wait<0>();
    __syncthreads();
    if (i + 1 < nIter) loadStage(i + 1);

    const uint32_t sa  = sb + (uint32_t)(i & 1) * STAGE_BYTES;
    const uint32_t sbB = sa + 16384;
#pragma unroll
    for (int ks = 0; ks < 4; ks++) {
      uint32_t afr[2][4];
#pragma unroll
      for (int mt = 0; mt < 2; mt++) {
        int row = arow + mt * 16;
        int ch  = 2 * ks + ach;
        ldsm4(afr[mt], sa + row * 128 + (((uint32_t)(ch ^ (row & 7))) << 4));
      }
      uint32_t bfr[4][4];
#pragma unroll
      for (int nt = 0; nt < 4; nt++) {
        int row = brow + nt * 16;
        int ch  = 2 * ks + bch;
        ldsm4(bfr[nt], sbB + row * 128 + (((uint32_t)(ch ^ (row & 7))) << 4));
      }
#pragma unroll
      for (int mt = 0; mt < 2; mt++)
#pragma unroll
        for (int n8 = 0; n8 < 8; n8++)
          mma16816(acc[mt][n8], afr[mt], &bfr[n8 >> 1][(n8 & 1) * 2]);
    }
  }

  const int crow = lane >> 2;
  const int ccol = (lane & 3) * 2;
  if (MODE == 1) {
    // cols 16b+c: c<8 -> gate_j, c>=8 -> val_j, j = 8b+c. n8 even gate, odd val.
    const int stride = N >> 1;
#pragma unroll
    for (int mt = 0; mt < 2; mt++) {
#pragma unroll
      for (int t = 0; t < 4; t++) {
        const float* gp = acc[mt][2*t];
        const float* vp = acc[mt][2*t+1];
        int j0   = ((bn + wn) >> 1) + 8*t + ccol;
        int row0 = bm + wm + mt*16 + crow;
        float o0 = gp[0] / (1.f + __expf(-gp[0])) * vp[0];
        float o1 = gp[1] / (1.f + __expf(-gp[1])) * vp[1];
        *(__half2*)&OUT[(size_t)row0 * stride + j0] = __floats2half2_rn(o0, o1);
        float o2 = gp[2] / (1.f + __expf(-gp[2])) * vp[2];
        float o3 = gp[3] / (1.f + __expf(-gp[3])) * vp[3];
        *(__half2*)&OUT[(size_t)(row0 + 8) * stride + j0] = __floats2half2_rn(o2, o3);
      }
    }
  } else if (MODE == 2) {
#pragma unroll
    for (int mt = 0; mt < 2; mt++) {
#pragma unroll
      for (int n8 = 0; n8 < 8; n8++) {
        int col  = bn + wn + n8 * 8 + ccol;
        int row0 = bm + wm + mt * 16 + crow;
        const float* ap = acc[mt][n8];
        *(__half2*)&OUT[(size_t)row0 * N + col]       = __floats2half2_rn(ap[0], ap[1]);
        *(__half2*)&OUT[(size_t)(row0 + 8) * N + col] = __floats2half2_rn(ap[2], ap[3]);
      }
    }
  } else {
#pragma unroll
    for (int mt = 0; mt < 2; mt++) {
#pragma unroll
      for (int n8 = 0; n8 < 8; n8++) {
        size_t r0 = (size_t)(bm + wm + mt * 16 + crow) * N + (bn + wn + n8 * 8 + ccol);
        *(float2*)&C[r0]                 = make_float2(acc[mt][n8][0], acc[mt][n8][1]);
        *(float2*)&C[r0 + (size_t)8 * N] = make_float2(acc[mt][n8][2], acc[mt][n8][3]);
      }
    }
  }
}

// ======================= windowed sigmoid attention (fp16 smem) ===============
// reads fp16 qkv [tok][1536]; k/v staged in smem as half2 [d2=0..31][tok],
// row stride AT_P2 half2. fp32 accumulation. writes fp16 msg into a2[tok][512].
#define AT_TOKS (128 + W_)   /* 160 */
#define AT_P2   161          /* half2 row stride */
#define ATTN_SMEM (2 * 32 * AT_P2 * 4)   /* 41216 B */

__global__ __launch_bounds__(128) void attn_kernel(
    const __half* __restrict__ qkv, __half* __restrict__ a2) {
  extern __shared__ __align__(16) char smc[];
  __half2* ks2 = (__half2*)smc;                 // [32][AT_P2]
  __half2* vs2 = ks2 + 32 * AT_P2;              // [32][AT_P2]
  const int c = blockIdx.x, h = blockIdx.y, b = blockIdx.z;
  const int base = c * 128 - W_;
  const int tid = threadIdx.x;

  // fill k/v tiles: per token 128 halves (k 64 | v 64) = 16 uint4 chunks
  for (int i4 = tid; i4 < AT_TOKS * 16; i4 += 128) {
    int tok   = i4 >> 4;
    int chunk = i4 & 15;
    int dq    = chunk * 8;            // half index 0..120
    int tg    = base + tok;
    uint4 raw = make_uint4(0u, 0u, 0u, 0u);
    if (tg >= 0)
      raw = *(const uint4*)&qkv[(size_t)(b*T_ + tg)*(3*D_) + D_ + h*128 + dq];
    __half2* sb2 = (dq < 64) ? ks2 : vs2;
    int r0 = (dq & 63) >> 1;          // half2 row
    const __half2* hv = (const __half2*)&raw;
    sb2[(r0+0)*AT_P2 + tok] = hv[0];
    sb2[(r0+1)*AT_P2 + tok] = hv[1];
    sb2[(r0+2)*AT_P2 + tok] = hv[2];
    sb2[(r0+3)*AT_P2 + tok] = hv[3];
  }
  __syncthreads();

  const int tg = c * 128 + tid;
  const __half* qp = &qkv[(size_t)(b*T_ + tg)*(3*D_) + h*HD_];
  float qr[64];
#pragma unroll
  for (int i = 0; i < 8; i++) {
    uint4 raw = *(const uint4*)(qp + 8*i);
    const __half2* hv = (const __half2*)&raw;
#pragma unroll
    for (int j = 0; j < 4; j++) {
      float2 f = __half22float2(hv[j]);
      qr[8*i + 2*j]     = f.x;
      qr[8*i + 2*j + 1] = f.y;
    }
  }
  float acc[64];
#pragma unroll
  for (int d = 0; d < 64; d++) acc[d] = 0.f;

  const int jt = tid + W_;
#pragma unroll 4
  for (int w = 0; w < W_; w += 2) {
    const int j0 = jt - 1 - w;
    const int j1 = jt - 2 - w;
    float s0=0.f, s1=0.f, u0=0.f, u1=0.f;
#pragma unroll
    for (int d2 = 0; d2 < 32; d2++) {
      float2 k0 = __half22float2(ks2[d2*AT_P2 + j0]);
      float2 k1 = __half22float2(ks2[d2*AT_P2 + j1]);
      s0 += qr[2*d2]   * k0.x;
      s1 += qr[2*d2+1] * k0.y;
      u0 += qr[2*d2]   * k1.x;
      u1 += qr[2*d2+1] * k1.y;
    }
    float tau0 = 1.f / (1.f + __expf(-(s0+s1) * 0.125f));
    float tau1 = 1.f / (1.f + __expf(-(u0+u1) * 0.125f));
#pragma unroll
    for (int d2 = 0; d2 < 32; d2++) {
      float2 v0 = __half22float2(vs2[d2*AT_P2 + j0]);
      float2 v1 = __half22float2(vs2[d2*AT_P2 + j1]);
      acc[2*d2]   += tau0 * v0.x + tau1 * v1.x;
      acc[2*d2+1] += tau0 * v0.y + tau1 * v1.y;
    }
  }

  size_t abase = (size_t)(b*T_ + tg) * D_;
  int off = h * HD_;
#pragma unroll
  for (int i = 0; i < 16; i++) {
    float4 v = make_float4(acc[4*i], acc[4*i+1], acc[4*i+2], acc[4*i+3]);
    *(uint2*)(a2 + abase + off + 4*i) = pack4h(v);
  }
}

// ======================= LayerNorm (+residual, +mod, +fp16 out) =======================
template<int MODE, int SPLIT>
__global__ __launch_bounds__(128) void ln_kernel(
    const float* __restrict__ x, const float* __restrict__ add,
    const float* __restrict__ g, const float* __restrict__ bb,
    const float* __restrict__ freqs, const float* __restrict__ phases,
    const float* __restrict__ amp, float* __restrict__ out,
    __half* __restrict__ a2) {
  const int row = blockIdx.x;
  const int i = threadIdx.x;
  float4 f = ((const float4*)(x + (size_t)row*D_))[i];
  if (MODE >= 1) {
    float4 a = ((const float4*)(add + (size_t)row*D_))[i];
    f.x+=a.x; f.y+=a.y; f.z+=a.z; f.w+=a.w;
  }
  float s  = f.x + f.y + f.z + f.w;
  float ss = f.x*f.x + f.y*f.y + f.z*f.z + f.w*f.w;
#pragma unroll
  for (int o = 16; o > 0; o >>= 1) {
    s  += __shfl_xor_sync(0xffffffffu, s,  o);
    ss += __shfl_xor_sync(0xffffffffu, ss, o);
  }
  __shared__ float rs[4], rss[4];
  if ((i & 31) == 0) { rs[i>>5] = s; rss[i>>5] = ss; }
  __syncthreads();
  s  = rs[0]  + rs[1]  + rs[2]  + rs[3];
  ss = rss[0] + rss[1] + rss[2] + rss[3];
  const float mu   = s * (1.f/D_);
  const float var  = ss * (1.f/D_) - mu*mu;
  const float rstd = rsqrtf(var + 1e-5f);
  float4 gv = ((const float4*)g)[i];
  float4 bv = ((const float4*)bb)[i];
  float4 o;
  o.x = (f.x-mu)*rstd*gv.x + bv.x;
  o.y = (f.y-mu)*rstd*gv.y + bv.y;
  o.z = (f.z-mu)*rstd*gv.z + bv.z;
  o.w = (f.w-mu)*rstd*gv.w + bv.w;
  if (MODE == 1) {
    float t  = (float)(row & (T_-1));
    float av = amp[0];
    float4 fr = ((const float4*)freqs)[i];
    float4 ph = ((const float4*)phases)[i];
    o.x *= 1.f + av*sinf(t*fr.x + ph.x);
    o.y *= 1.f + av*sinf(t*fr.y + ph.y);
    o.z *= 1.f + av*sinf(t*fr.z + ph.z);
    o.w *= 1.f + av*sinf(t*fr.w + ph.w);
  }
  ((float4*)(out + (size_t)row*D_))[i] = o;
  if (SPLIT) {
    *(uint2*)(a2 + (size_t)row * D_ + i * 4) = pack4h(o);
  }
}

// ======================= launch =======================
extern "C" void kernel_launch(void* const* d_in, const int* in_sizes, int n_in,
                              void* d_out, int out_size) {
  const float* x      = (const float*)d_in[0];
  const float* pre_g  = (const float*)d_in[1];
  const float* pre_b  = (const float*)d_in[2];
  const float* wq     = (const float*)d_in[3];
  const float* wkv    = (const float*)d_in[4];
  const float* wo     = (const float*)d_in[5];
  const float* attn_g = (const float*)d_in[6];
  const float* attn_b = (const float*)d_in[7];
  const float* freqs  = (const float*)d_in[8];
  const float* phases = (const float*)d_in[9];
  const float* amp    = (const float*)d_in[10];
  const float* w_gate = (const float*)d_in[11];
  const float* w_val  = (const float*)d_in[12];
  const float* w_proj = (const float*)d_in[13];
  const float* ffn_g  = (const float*)d_in[14];
  const float* ffn_b  = (const float*)d_in[15];

  float *h, *tmp, *y, *z;
  __half *qkvh, *a2, *a3, *b2;
  cudaGetSymbolAddress((void**)&h,    g_h);
  cudaGetSymbolAddress((void**)&tmp,  g_tmp);
  cudaGetSymbolAddress((void**)&y,    g_y);
  cudaGetSymbolAddress((void**)&z,    g_z);
  cudaGetSymbolAddress((void**)&qkvh, g_qkvh);
  cudaGetSymbolAddress((void**)&a2,   g_a2);
  cudaGetSymbolAddress((void**)&a3,   g_a3);
  cudaGetSymbolAddress((void**)&b2,   g_b2);

  cudaFuncSetAttribute(attn_kernel, cudaFuncAttributeMaxDynamicSharedMemorySize, ATTN_SMEM);
  cudaFuncSetAttribute(gemm_mma<0>, cudaFuncAttributeMaxDynamicSharedMemorySize, GEMM_DYN_SMEM);
  cudaFuncSetAttribute(gemm_mma<1>, cudaFuncAttributeMaxDynamicSharedMemorySize, GEMM_DYN_SMEM);
  cudaFuncSetAttribute(gemm_mma<2>, cudaFuncAttributeMaxDynamicSharedMemorySize, GEMM_DYN_SMEM);

  // 1) h = LN(x) (+ fp16 copy into a2, K=512)
  ln_kernel<0,1><<<NTOK, 128>>>(x, nullptr, pre_g, pre_b, nullptr, nullptr, nullptr, h, a2);

  // 2) qkv = h @ [wq | wkv], N=1536, K=512, fp16 output
  split_bt_kernel<<<dim3(D_/32,   D_/32), dim3(32,32)>>>(wq,  b2,                    D_, D_);
  split_bt_kernel<<<dim3(2*D_/32, D_/32), dim3(32,32)>>>(wkv, b2 + (size_t)D_ * D_,  D_, 2*D_);
  gemm_mma<2><<<dim3(12, 64), 256, GEMM_DYN_SMEM>>>(a2, b2, nullptr, qkvh, 3*D_, D_);

  // 3) attention -> fp16 msg into a2
  attn_kernel<<<dim3(T_/128, H_, B_), 128, ATTN_SMEM>>>(qkvh, a2);

  // 4) tmp = msg@wo ; y = LN(h+tmp)*(1+amp*sin) (+ fp16 into a2)
  split_bt_kernel<<<dim3(D_/32, D_/32), dim3(32,32)>>>(wo, b2, D_, D_);
  gemm_mma<0><<<dim3(4, 64), 256, GEMM_DYN_SMEM>>>(a2, b2, tmp, nullptr, D_, D_);
  ln_kernel<1,1><<<NTOK, 128>>>(h, tmp, attn_g, attn_b, freqs, phases, amp, y, a2);

  // 5) FFN: fused gv GEMM (gate/val interleaved, silu epilogue -> a3 fp16)
  split_bt_ilv_kernel<<<dim3(HID_/32, D_/32), dim3(32,32)>>>(w_gate, b2, D_, HID_, 0);
  split_bt_ilv_kernel<<<dim3(HID_/32, D_/32), dim3(32,32)>>>(w_val,  b2, D_, HID_, 8);
  gemm_mma<1><<<dim3(24, 64), 256, GEMM_DYN_SMEM>>>(a2, b2, nullptr, a3, 2*HID_, D_);

  // z = a3 @ w_proj, N=512, K=1536
  split_bt_kernel<<<dim3(D_/32, HID_/32), dim3(32,32)>>>(w_proj, b2, HID_, D_);
  gemm_mma<0><<<dim3(4, 64), 256, GEMM_DYN_SMEM>>>(a3, b2, z, nullptr, D_, HID_);

  // 6) out = LN(y + z)
  ln_kernel<2,0><<<NTOK, 128>>>(y, z, ffn_g, ffn_b, nullptr, nullptr, nullptr, (float*)d_out, nullptr);
}

// round 10
// speedup vs baseline: 1.0480x; 1.0463x over previous
#include <cuda_runtime.h>
#include <cuda_fp16.h>
#include <math.h>
#include <stdint.h>

#define B_   2
#define T_   4096
#define D_   512
#define H_   8
#define HD_  64
#define W_   32
#define HID_ 1536
#define NTOK (B_*T_)

// ---------------- scratch (device globals; no allocs allowed) ----------------
__device__ __half g_h   [(size_t)NTOK * D_];         // LN1 out (residual + GEMM A)
__device__ __half g_qkvh[(size_t)NTOK * 3 * D_];     // fp16 qkv
__device__ __half g_msg [(size_t)NTOK * D_];         // attn out
__device__ __half g_tmp [(size_t)NTOK * D_];         // msg @ wo
__device__ __half g_y   [(size_t)NTOK * D_];         // LN2 out (residual + GEMM A)
__device__ __half g_a3  [(size_t)NTOK * HID_];       // silu(gate)*val
__device__ __half g_z   [(size_t)NTOK * D_];         // a3 @ w_proj
__device__ __half g_b2  [(size_t)3355443];           // fp16 B^T

// ======================= PTX helpers (baseline ISA only) =======================
__device__ __forceinline__ uint32_t s2u(const void* p) {
  uint32_t a;
  asm("{ .reg .u64 t; cvta.to.shared.u64 t, %1; cvt.u32.u64 %0, t; }" : "=r"(a) : "l"(p));
  return a;
}
__device__ __forceinline__ void cp16(uint32_t dst, const void* src) {
  asm volatile("cp.async.cg.shared.global [%0], [%1], 16;" :: "r"(dst), "l"(src) : "memory");
}
__device__ __forceinline__ void cp_commit() { asm volatile("cp.async.commit_group;" ::: "memory"); }
template<int N>
__device__ __forceinline__ void cp_wait() { asm volatile("cp.async.wait_group %0;" :: "n"(N) : "memory"); }

__device__ __forceinline__ void ldsm4(uint32_t* r, uint32_t addr) {
  asm volatile("ldmatrix.sync.aligned.m8n8.x4.shared.b16 {%0,%1,%2,%3}, [%4];"
               : "=r"(r[0]), "=r"(r[1]), "=r"(r[2]), "=r"(r[3]) : "r"(addr));
}
__device__ __forceinline__ void mma16816(float* d, const uint32_t* a, const uint32_t* b) {
  asm volatile(
      "mma.sync.aligned.m16n8k16.row.col.f32.f16.f16.f32 "
      "{%0,%1,%2,%3}, {%4,%5,%6,%7}, {%8,%9}, {%0,%1,%2,%3};"
      : "+f"(d[0]), "+f"(d[1]), "+f"(d[2]), "+f"(d[3])
      : "r"(a[0]), "r"(a[1]), "r"(a[2]), "r"(a[3]), "r"(b[0]), "r"(b[1]));
}

__device__ __forceinline__ uint2 pack4h(const float4& v) {
  union { __half b[4]; uint2 u; } hu;
  hu.b[0] = __float2half_rn(v.x); hu.b[1] = __float2half_rn(v.y);
  hu.b[2] = __float2half_rn(v.z); hu.b[3] = __float2half_rn(v.w);
  return hu.u;
}
__device__ __forceinline__ float4 unpack4h(uint2 u) {
  float2 a = __half22float2(*(__half2*)&u.x);
  float2 b = __half22float2(*(__half2*)&u.y);
  return make_float4(a.x, a.y, b.x, b.y);
}

// ======================= weight transpose to fp16: w[K,N] -> out[n][K] ======
__global__ void split_bt_kernel(const float* __restrict__ w,
                                __half* __restrict__ out, int K, int N) {
  __shared__ float t[32][33];
  int n0 = blockIdx.x * 32, k0 = blockIdx.y * 32;
  t[threadIdx.y][threadIdx.x] = w[(size_t)(k0 + threadIdx.y) * N + n0 + threadIdx.x];
  __syncthreads();
  int n = n0 + threadIdx.y, k = k0 + threadIdx.x;
  out[(size_t)n * K + k] = __float2half_rn(t[threadIdx.x][threadIdx.y]);
}

// interleaved variant for gate/val: logical col j -> B2 row (j/8)*16 + j%8 + off
__global__ void split_bt_ilv_kernel(const float* __restrict__ w,
                                    __half* __restrict__ out, int K, int N, int off) {
  __shared__ float t[32][33];
  int n0 = blockIdx.x * 32, k0 = blockIdx.y * 32;
  t[threadIdx.y][threadIdx.x] = w[(size_t)(k0 + threadIdx.y) * N + n0 + threadIdx.x];
  __syncthreads();
  int j = n0 + threadIdx.y, k = k0 + threadIdx.x;
  int r = ((j >> 3) << 4) + (j & 7) + off;
  out[(size_t)r * K + k] = __float2half_rn(t[threadIdx.x][threadIdx.y]);
}

// ======================= mma.sync fp16 GEMM (R7-proven config) =======================
// C[M,N] = A2[M,K] @ B2[N,K]^T. CTA tile 128x128, BK=64, 2-stage double buffer,
// 256 threads / 8 warps, warp tile 32x64.
// MODE 1: silu(gate)*val -> half OUT[M,N/2] (interleaved B).  MODE 2: half OUT[M,N].
#define STAGE_BYTES 32768          /* A 16KB + B 16KB */
#define GEMM_DYN_SMEM (2*STAGE_BYTES + 1024)

template<int MODE>
__global__ __launch_bounds__(256, 2) void gemm_mma(
    const __half* __restrict__ A2, const __half* __restrict__ B2,
    __half* __restrict__ OUT, int N, int K) {
  extern __shared__ char smraw[];
  uint32_t sb0 = s2u(smraw);
  const uint32_t sb = sb0 + ((1024u - (sb0 & 1023u)) & 1023u);

  const int tid = threadIdx.x, lane = tid & 31, wid = tid >> 5;
  const int bm = blockIdx.y * 128, bn = blockIdx.x * 128;
  const int wm = (wid >> 1) * 32, wn = (wid & 1) * 64;

  uint32_t aOff[4], bOff[4];
  const char *aSrc[4], *bSrc[4];
#pragma unroll
  for (int j = 0; j < 4; j++) {
    int s = tid + j * 256, r = s >> 3, c = s & 7;
    uint32_t off = (uint32_t)(r * 128 + ((c ^ (r & 7)) << 4));
    aOff[j] = off;
    bOff[j] = off;
    aSrc[j] = (const char*)(A2 + (size_t)(bm + r) * K) + c * 16;
    bSrc[j] = (const char*)(B2 + (size_t)(bn + r) * K) + c * 16;
  }

  float acc[2][8][4];
#pragma unroll
  for (int mt = 0; mt < 2; mt++)
#pragma unroll
    for (int nt = 0; nt < 8; nt++)
#pragma unroll
      for (int e = 0; e < 4; e++) acc[mt][nt][e] = 0.f;

  const int arow = wm + (lane & 15);
  const int ach  = lane >> 4;
  const int brow = wn + (lane & 7) + ((lane >> 1) & 8);
  const int bch  = (lane >> 3) & 1;

  const int nIter = K >> 6;

  auto loadStage = [&](int i) {
    uint32_t st = sb + (uint32_t)(i & 1) * STAGE_BYTES;
    size_t koff = (size_t)i * 128;
#pragma unroll
    for (int j = 0; j < 4; j++) cp16(st + aOff[j], aSrc[j] + koff);
#pragma unroll
    for (int j = 0; j < 4; j++) cp16(st + 16384 + bOff[j], bSrc[j] + koff);
    cp_commit();
  };

  loadStage(0);

  for (int i = 0; i < nIter; i++) {
    cp_wait<0>();
    __syncthreads();
    if (i + 1 < nIter) loadStage(i + 1);

    const uint32_t sa  = sb + (uint32_t)(i & 1) * STAGE_BYTES;
    const uint32_t sbB = sa + 16384;
#pragma unroll
    for (int ks = 0; ks < 4; ks++) {
      uint32_t afr[2][4];
#pragma unroll
      for (int mt = 0; mt < 2; mt++) {
        int row = arow + mt * 16;
        int ch  = 2 * ks + ach;
        ldsm4(afr[mt], sa + row * 128 + (((uint32_t)(ch ^ (row & 7))) << 4));
      }
      uint32_t bfr[4][4];
#pragma unroll
      for (int nt = 0; nt < 4; nt++) {
        int row = brow + nt * 16;
        int ch  = 2 * ks + bch;
        ldsm4(bfr[nt], sbB + row * 128 + (((uint32_t)(ch ^ (row & 7))) << 4));
      }
#pragma unroll
      for (int mt = 0; mt < 2; mt++)
#pragma unroll
        for (int n8 = 0; n8 < 8; n8++)
          mma16816(acc[mt][n8], afr[mt], &bfr[n8 >> 1][(n8 & 1) * 2]);
    }
  }

  const int crow = lane >> 2;
  const int ccol = (lane & 3) * 2;
  if (MODE == 1) {
    // cols 16b+c: c<8 -> gate_j, c>=8 -> val_j, j = 8b+c. n8 even gate, odd val.
    const int stride = N >> 1;
#pragma unroll
    for (int mt = 0; mt < 2; mt++) {
#pragma unroll
      for (int t = 0; t < 4; t++) {
        const float* gp = acc[mt][2*t];
        const float* vp = acc[mt][2*t+1];
        int j0   = ((bn + wn) >> 1) + 8*t + ccol;
        int row0 = bm + wm + mt*16 + crow;
        float o0 = gp[0] / (1.f + __expf(-gp[0])) * vp[0];
        float o1 = gp[1] / (1.f + __expf(-gp[1])) * vp[1];
        *(__half2*)&OUT[(size_t)row0 * stride + j0] = __floats2half2_rn(o0, o1);
        float o2 = gp[2] / (1.f + __expf(-gp[2])) * vp[2];
        float o3 = gp[3] / (1.f + __expf(-gp[3])) * vp[3];
        *(__half2*)&OUT[(size_t)(row0 + 8) * stride + j0] = __floats2half2_rn(o2, o3);
      }
    }
  } else {
#pragma unroll
    for (int mt = 0; mt < 2; mt++) {
#pragma unroll
      for (int n8 = 0; n8 < 8; n8++) {
        int col  = bn + wn + n8 * 8 + ccol;
        int row0 = bm + wm + mt * 16 + crow;
        const float* ap = acc[mt][n8];
        *(__half2*)&OUT[(size_t)row0 * N + col]       = __floats2half2_rn(ap[0], ap[1]);
        *(__half2*)&OUT[(size_t)(row0 + 8) * N + col] = __floats2half2_rn(ap[2], ap[3]);
      }
    }
  }
}

// ======================= windowed sigmoid attention =======================
// R7 structure: fp32 smem k/v tiles, 8 independent FMA chains. fp16 qkv input is
// converted ONCE during the smem fill; the hot loop is pure fp32 LDS + FMA.
#define AT_TOKS (128 + W_)   /* 160 */
#define AT_PAD  161
#define ATTN_SMEM (2 * 64 * AT_PAD * 4)   /* 82432 B */

__global__ __launch_bounds__(128) void attn_kernel(
    const __half* __restrict__ qkv, __half* __restrict__ msg) {
  extern __shared__ float smf[];
  float* ks = smf;
  float* vs = smf + 64 * AT_PAD;
  const int c = blockIdx.x, h = blockIdx.y, b = blockIdx.z;
  const int base = c * 128 - W_;
  const int tid = threadIdx.x;

  for (int i4 = tid; i4 < AT_TOKS * 32; i4 += 128) {
    int tok = i4 >> 5;
    int dq  = (i4 & 31) << 2;
    int tg  = base + tok;
    float4 v = make_float4(0.f, 0.f, 0.f, 0.f);
    if (tg >= 0)
      v = unpack4h(*(const uint2*)&qkv[(size_t)(b*T_ + tg)*(3*D_) + D_ + h*128 + dq]);
    float* dst = (dq < 64) ? (ks + dq*AT_PAD + tok) : (vs + (dq-64)*AT_PAD + tok);
    dst[0]        = v.x;
    dst[AT_PAD]   = v.y;
    dst[2*AT_PAD] = v.z;
    dst[3*AT_PAD] = v.w;
  }
  __syncthreads();

  const int tg = c * 128 + tid;
  const __half* qp = &qkv[(size_t)(b*T_ + tg)*(3*D_) + h*HD_];
  float qr[64];
#pragma unroll
  for (int i = 0; i < 16; i++) {
    float4 f = unpack4h(*(const uint2*)(qp + 4*i));
    qr[4*i]=f.x; qr[4*i+1]=f.y; qr[4*i+2]=f.z; qr[4*i+3]=f.w;
  }
  float acc[64];
#pragma unroll
  for (int d = 0; d < 64; d++) acc[d] = 0.f;

  const int jt = tid + W_;
#pragma unroll 4
  for (int w = 0; w < W_; w += 2) {
    const int j0 = jt - 1 - w;
    const int j1 = jt - 2 - w;
    float s0=0.f, s1=0.f, s2=0.f, s3=0.f;
    float u0=0.f, u1=0.f, u2=0.f, u3=0.f;
#pragma unroll
    for (int d = 0; d < 64; d += 4) {
      s0 += qr[d]   * ks[(d)  *AT_PAD + j0];
      s1 += qr[d+1] * ks[(d+1)*AT_PAD + j0];
      s2 += qr[d+2] * ks[(d+2)*AT_PAD + j0];
      s3 += qr[d+3] * ks[(d+3)*AT_PAD + j0];
      u0 += qr[d]   * ks[(d)  *AT_PAD + j1];
      u1 += qr[d+1] * ks[(d+1)*AT_PAD + j1];
      u2 += qr[d+2] * ks[(d+2)*AT_PAD + j1];
      u3 += qr[d+3] * ks[(d+3)*AT_PAD + j1];
    }
    float sA = (s0+s1) + (s2+s3);
    float sB = (u0+u1) + (u2+u3);
    float tau0 = 1.f / (1.f + __expf(-sA * 0.125f));
    float tau1 = 1.f / (1.f + __expf(-sB * 0.125f));
#pragma unroll
    for (int d = 0; d < 64; d++)
      acc[d] += tau0 * vs[d*AT_PAD + j0] + tau1 * vs[d*AT_PAD + j1];
  }

  size_t abase = (size_t)(b*T_ + tg) * D_;
  int off = h * HD_;
#pragma unroll
  for (int i = 0; i < 16; i++) {
    float4 v = make_float4(acc[4*i], acc[4*i+1], acc[4*i+2], acc[4*i+3]);
    *(uint2*)(msg + abase + off + 4*i) = pack4h(v);
  }
}

// ======================= LayerNorm =======================
// MODE 0: fp32 x -> fp16 out = LN(x)
// MODE 1: fp16 x,add -> fp16 out = LN(x+add) * (1 + amp*sin(t*freqs+phases))
// MODE 2: fp16 x,add -> fp32 out = LN(x+add)
template<int MODE>
__global__ __launch_bounds__(128) void ln_kernel(
    const void* __restrict__ xv, const __half* __restrict__ add,
    const float* __restrict__ g, const float* __restrict__ bb,
    const float* __restrict__ freqs, const float* __restrict__ phases,
    const float* __restrict__ amp, void* __restrict__ outv) {
  const int row = blockIdx.x;
  const int i = threadIdx.x;
  float4 f;
  if (MODE == 0) {
    f = ((const float4*)((const float*)xv + (size_t)row*D_))[i];
  } else {
    f = unpack4h(((const uint2*)((const __half*)xv + (size_t)row*D_))[i]);
    float4 a = unpack4h(((const uint2*)(add + (size_t)row*D_))[i]);
    f.x+=a.x; f.y+=a.y; f.z+=a.z; f.w+=a.w;
  }
  float s  = f.x + f.y + f.z + f.w;
  float ss = f.x*f.x + f.y*f.y + f.z*f.z + f.w*f.w;
#pragma unroll
  for (int o = 16; o > 0; o >>= 1) {
    s  += __shfl_xor_sync(0xffffffffu, s,  o);
    ss += __shfl_xor_sync(0xffffffffu, ss, o);
  }
  __shared__ float rs[4], rss[4];
  if ((i & 31) == 0) { rs[i>>5] = s; rss[i>>5] = ss; }
  __syncthreads();
  s  = rs[0]  + rs[1]  + rs[2]  + rs[3];
  ss = rss[0] + rss[1] + rss[2] + rss[3];
  const float mu   = s * (1.f/D_);
  const float var  = ss * (1.f/D_) - mu*mu;
  const float rstd = rsqrtf(var + 1e-5f);
  float4 gv = ((const float4*)g)[i];
  float4 bv = ((const float4*)bb)[i];
  float4 o;
  o.x = (f.x-mu)*rstd*gv.x + bv.x;
  o.y = (f.y-mu)*rstd*gv.y + bv.y;
  o.z = (f.z-mu)*rstd*gv.z + bv.z;
  o.w = (f.w-mu)*rstd*gv.w + bv.w;
  if (MODE == 1) {
    float t  = (float)(row & (T_-1));
    float av = amp[0];
    float4 fr = ((const float4*)freqs)[i];
    float4 ph = ((const float4*)phases)[i];
    o.x *= 1.f + av*sinf(t*fr.x + ph.x);
    o.y *= 1.f + av*sinf(t*fr.y + ph.y);
    o.z *= 1.f + av*sinf(t*fr.z + ph.z);
    o.w *= 1.f + av*sinf(t*fr.w + ph.w);
  }
  if (MODE == 2) {
    ((float4*)((float*)outv + (size_t)row*D_))[i] = o;
  } else {
    ((uint2*)((__half*)outv + (size_t)row*D_))[i] = pack4h(o);
  }
}

// ======================= launch =======================
extern "C" void kernel_launch(void* const* d_in, const int* in_sizes, int n_in,
                              void* d_out, int out_size) {
  const float* x      = (const float*)d_in[0];
  const float* pre_g  = (const float*)d_in[1];
  const float* pre_b  = (const float*)d_in[2];
  const float* wq     = (const float*)d_in[3];
  const float* wkv    = (const float*)d_in[4];
  const float* wo     = (const float*)d_in[5];
  const float* attn_g = (const float*)d_in[6];
  const float* attn_b = (const float*)d_in[7];
  const float* freqs  = (const float*)d_in[8];
  const float* phases = (const float*)d_in[9];
  const float* amp    = (const float*)d_in[10];
  const float* w_gate = (const float*)d_in[11];
  const float* w_val  = (const float*)d_in[12];
  const float* w_proj = (const float*)d_in[13];
  const float* ffn_g  = (const float*)d_in[14];
  const float* ffn_b  = (const float*)d_in[15];

  __half *h, *qkvh, *msg, *tmp, *y, *a3, *z, *b2;
  cudaGetSymbolAddress((void**)&h,    g_h);
  cudaGetSymbolAddress((void**)&qkvh, g_qkvh);
  cudaGetSymbolAddress((void**)&msg,  g_msg);
  cudaGetSymbolAddress((void**)&tmp,  g_tmp);
  cudaGetSymbolAddress((void**)&y,    g_y);
  cudaGetSymbolAddress((void**)&a3,   g_a3);
  cudaGetSymbolAddress((void**)&z,    g_z);
  cudaGetSymbolAddress((void**)&b2,   g_b2);

  cudaFuncSetAttribute(attn_kernel, cudaFuncAttributeMaxDynamicSharedMemorySize, ATTN_SMEM);
  cudaFuncSetAttribute(gemm_mma<1>, cudaFuncAttributeMaxDynamicSharedMemorySize, GEMM_DYN_SMEM);
  cudaFuncSetAttribute(gemm_mma<2>, cudaFuncAttributeMaxDynamicSharedMemorySize, GEMM_DYN_SMEM);

  // 1) h = LN(x)  (fp16, single buffer: residual + GEMM A)
  ln_kernel<0><<<NTOK, 128>>>(x, nullptr, pre_g, pre_b, nullptr, nullptr, nullptr, h);

  // 2) qkv = h @ [wq | wkv], N=1536, K=512, fp16 out
  split_bt_kernel<<<dim3(D_/32,   D_/32), dim3(32,32)>>>(wq,  b2,                    D_, D_);
  split_bt_kernel<<<dim3(2*D_/32, D_/32), dim3(32,32)>>>(wkv, b2 + (size_t)D_ * D_,  D_, 2*D_);
  gemm_mma<2><<<dim3(12, 64), 256, GEMM_DYN_SMEM>>>(h, b2, qkvh, 3*D_, D_);

  // 3) attention -> fp16 msg
  attn_kernel<<<dim3(T_/128, H_, B_), 128, ATTN_SMEM>>>(qkvh, msg);

  // 4) tmp = msg@wo (fp16) ; y = LN(h+tmp)*(1+amp*sin) (fp16)
  split_bt_kernel<<<dim3(D_/32, D_/32), dim3(32,32)>>>(wo, b2, D_, D_);
  gemm_mma<2><<<dim3(4, 64), 256, GEMM_DYN_SMEM>>>(msg, b2, tmp, D_, D_);
  ln_kernel<1><<<NTOK, 128>>>(h, tmp, attn_g, attn_b, freqs, phases, amp, y);

  // 5) FFN: fused gv GEMM (gate/val interleaved, silu epilogue -> a3 fp16)
  split_bt_ilv_kernel<<<dim3(HID_/32, D_/32), dim3(32,32)>>>(w_gate, b2, D_, HID_, 0);
  split_bt_ilv_kernel<<<dim3(HID_/32, D_/32), dim3(32,32)>>>(w_val,  b2, D_, HID_, 8);
  gemm_mma<1><<<dim3(24, 64), 256, GEMM_DYN_SMEM>>>(y, b2, a3, 2*HID_, D_);

  // z = a3 @ w_proj (fp16), N=512, K=1536
  split_bt_kernel<<<dim3(D_/32, HID_/32), dim3(32,32)>>>(w_proj, b2, HID_, D_);
  gemm_mma<2><<<dim3(4, 64), 256, GEMM_DYN_SMEM>>>(a3, b2, z, D_, HID_);

  // 6) out = LN(y + z)  (fp32 output)
  ln_kernel<2><<<NTOK, 128>>>(y, z, ffn_g, ffn_b, nullptr, nullptr, nullptr, d_out);
}

// round 11
// speedup vs baseline: 1.0830x; 1.0334x over previous
#include <cuda_runtime.h>
#include <cuda_fp16.h>
#include <math.h>
#include <stdint.h>

#define B_   2
#define T_   4096
#define D_   512
#define H_   8
#define HD_  64
#define W_   32
#define HID_ 1536
#define NTOK (B_*T_)

// ---------------- scratch (device globals; no allocs allowed) ----------------
__device__ __half g_h   [(size_t)NTOK * D_];         // LN1 out (residual + GEMM A)
__device__ __half g_qkvh[(size_t)NTOK * 3 * D_];     // fp16 qkv
__device__ __half g_msg [(size_t)NTOK * D_];         // attn out
__device__ __half g_tmp [(size_t)NTOK * D_];         // msg @ wo
__device__ __half g_y   [(size_t)NTOK * D_];         // LN2 out (residual + GEMM A)
__device__ __half g_a3  [(size_t)NTOK * HID_];       // silu(gate)*val
__device__ __half g_z   [(size_t)NTOK * D_];         // a3 @ w_proj
// fp16 B^T regions (disjoint so all conversions can run up-front on a side stream)
#define B2_QKV  0                         /* 1536 x 512  = 786432  */
#define B2_WO   786432                    /* 512  x 512  = 262144  */
#define B2_GV   1048576                   /* 3072 x 512  = 1572864 */
#define B2_PROJ 2621440                   /* 512  x 1536 = 786432  */
__device__ __half g_b2[(size_t)3407872];

// ======================= PTX helpers (baseline ISA only) =======================
__device__ __forceinline__ uint32_t s2u(const void* p) {
  uint32_t a;
  asm("{ .reg .u64 t; cvta.to.shared.u64 t, %1; cvt.u32.u64 %0, t; }" : "=r"(a) : "l"(p));
  return a;
}
__device__ __forceinline__ void cp16(uint32_t dst, const void* src) {
  asm volatile("cp.async.cg.shared.global [%0], [%1], 16;" :: "r"(dst), "l"(src) : "memory");
}
__device__ __forceinline__ void cp_commit() { asm volatile("cp.async.commit_group;" ::: "memory"); }
template<int N>
__device__ __forceinline__ void cp_wait() { asm volatile("cp.async.wait_group %0;" :: "n"(N) : "memory"); }

__device__ __forceinline__ void ldsm4(uint32_t* r, uint32_t addr) {
  asm volatile("ldmatrix.sync.aligned.m8n8.x4.shared.b16 {%0,%1,%2,%3}, [%4];"
               : "=r"(r[0]), "=r"(r[1]), "=r"(r[2]), "=r"(r[3]) : "r"(addr));
}
__device__ __forceinline__ void mma16816(float* d, const uint32_t* a, const uint32_t* b) {
  asm volatile(
      "mma.sync.aligned.m16n8k16.row.col.f32.f16.f16.f32 "
      "{%0,%1,%2,%3}, {%4,%5,%6,%7}, {%8,%9}, {%0,%1,%2,%3};"
      : "+f"(d[0]), "+f"(d[1]), "+f"(d[2]), "+f"(d[3])
      : "r"(a[0]), "r"(a[1]), "r"(a[2]), "r"(a[3]), "r"(b[0]), "r"(b[1]));
}

__device__ __forceinline__ uint2 pack4h(const float4& v) {
  union { __half b[4]; uint2 u; } hu;
  hu.b[0] = __float2half_rn(v.x); hu.b[1] = __float2half_rn(v.y);
  hu.b[2] = __float2half_rn(v.z); hu.b[3] = __float2half_rn(v.w);
  return hu.u;
}
__device__ __forceinline__ float4 unpack4h(uint2 u) {
  float2 a = __half22float2(*(__half2*)&u.x);
  float2 b = __half22float2(*(__half2*)&u.y);
  return make_float4(a.x, a.y, b.x, b.y);
}

// ======================= weight transpose to fp16: w[K,N] -> out[n][K] ======
__global__ void split_bt_kernel(const float* __restrict__ w,
                                __half* __restrict__ out, int K, int N) {
  __shared__ float t[32][33];
  int n0 = blockIdx.x * 32, k0 = blockIdx.y * 32;
  t[threadIdx.y][threadIdx.x] = w[(size_t)(k0 + threadIdx.y) * N + n0 + threadIdx.x];
  __syncthreads();
  int n = n0 + threadIdx.y, k = k0 + threadIdx.x;
  out[(size_t)n * K + k] = __float2half_rn(t[threadIdx.x][threadIdx.y]);
}

// interleaved variant for gate/val: logical col j -> B2 row (j/8)*16 + j%8 + off
__global__ void split_bt_ilv_kernel(const float* __restrict__ w,
                                    __half* __restrict__ out, int K, int N, int off) {
  __shared__ float t[32][33];
  int n0 = blockIdx.x * 32, k0 = blockIdx.y * 32;
  t[threadIdx.y][threadIdx.x] = w[(size_t)(k0 + threadIdx.y) * N + n0 + threadIdx.x];
  __syncthreads();
  int j = n0 + threadIdx.y, k = k0 + threadIdx.x;
  int r = ((j >> 3) << 4) + (j & 7) + off;
  out[(size_t)r * K + k] = __float2half_rn(t[threadIdx.x][threadIdx.y]);
}

// ======================= mma.sync fp16 GEMM (R7-proven config) =======================
// C[M,N] = A2[M,K] @ B2[N,K]^T. CTA tile 128x128, BK=64, 2-stage double buffer,
// 256 threads / 8 warps, warp tile 32x64.
// MODE 1: silu(gate)*val -> half OUT[M,N/2] (interleaved B).  MODE 2: half OUT[M,N].
#define STAGE_BYTES 32768          /* A 16KB + B 16KB */
#define GEMM_DYN_SMEM (2*STAGE_BYTES + 1024)

template<int MODE>
__global__ __launch_bounds__(256, 2) void gemm_mma(
    const __half* __restrict__ A2, const __half* __restrict__ B2,
    __half* __restrict__ OUT, int N, int K) {
  extern __shared__ char smraw[];
  uint32_t sb0 = s2u(smraw);
  const uint32_t sb = sb0 + ((1024u - (sb0 & 1023u)) & 1023u);

  const int tid = threadIdx.x, lane = tid & 31, wid = tid >> 5;
  const int bm = blockIdx.y * 128, bn = blockIdx.x * 128;
  const int wm = (wid >> 1) * 32, wn = (wid & 1) * 64;

  uint32_t aOff[4], bOff[4];
  const char *aSrc[4], *bSrc[4];
#pragma unroll
  for (int j = 0; j < 4; j++) {
    int s = tid + j * 256, r = s >> 3, c = s & 7;
    uint32_t off = (uint32_t)(r * 128 + ((c ^ (r & 7)) << 4));
    aOff[j] = off;
    bOff[j] = off;
    aSrc[j] = (const char*)(A2 + (size_t)(bm + r) * K) + c * 16;
    bSrc[j] = (const char*)(B2 + (size_t)(bn + r) * K) + c * 16;
  }

  float acc[2][8][4];
#pragma unroll
  for (int mt = 0; mt < 2; mt++)
#pragma unroll
    for (int nt = 0; nt < 8; nt++)
#pragma unroll
      for (int e = 0; e < 4; e++) acc[mt][nt][e] = 0.f;

  const int arow = wm + (lane & 15);
  const int ach  = lane >> 4;
  const int brow = wn + (lane & 7) + ((lane >> 1) & 8);
  const int bch  = (lane >> 3) & 1;

  const int nIter = K >> 6;

  auto loadStage = [&](int i) {
    uint32_t st = sb + (uint32_t)(i & 1) * STAGE_BYTES;
    size_t koff = (size_t)i * 128;
#pragma unroll
    for (int j = 0; j < 4; j++) cp16(st + aOff[j], aSrc[j] + koff);
#pragma unroll
    for (int j = 0; j < 4; j++) cp16(st + 16384 + bOff[j], bSrc[j] + koff);
    cp_commit();
  };

  loadStage(0);

  for (int i = 0; i < nIter; i++) {
    cp_wait<0>();
    __syncthreads();
    if (i + 1 < nIter) loadStage(i + 1);

    const uint32_t sa  = sb + (uint32_t)(i & 1) * STAGE_BYTES;
    const uint32_t sbB = sa + 16384;
#pragma unroll
    for (int ks = 0; ks < 4; ks++) {
      uint32_t afr[2][4];
#pragma unroll
      for (int mt = 0; mt < 2; mt++) {
        int row = arow + mt * 16;
        int ch  = 2 * ks + ach;
        ldsm4(afr[mt], sa + row * 128 + (((uint32_t)(ch ^ (row & 7))) << 4));
      }
      uint32_t bfr[4][4];
#pragma unroll
      for (int nt = 0; nt < 4; nt++) {
        int row = brow + nt * 16;
        int ch  = 2 * ks + bch;
        ldsm4(bfr[nt], sbB + row * 128 + (((uint32_t)(ch ^ (row & 7))) << 4));
      }
#pragma unroll
      for (int mt = 0; mt < 2; mt++)
#pragma unroll
        for (int n8 = 0; n8 < 8; n8++)
          mma16816(acc[mt][n8], afr[mt], &bfr[n8 >> 1][(n8 & 1) * 2]);
    }
  }

  const int crow = lane >> 2;
  const int ccol = (lane & 3) * 2;
  if (MODE == 1) {
    // cols 16b+c: c<8 -> gate_j, c>=8 -> val_j, j = 8b+c. n8 even gate, odd val.
    const int stride = N >> 1;
#pragma unroll
    for (int mt = 0; mt < 2; mt++) {
#pragma unroll
      for (int t = 0; t < 4; t++) {
        const float* gp = acc[mt][2*t];
        const float* vp = acc[mt][2*t+1];
        int j0   = ((bn + wn) >> 1) + 8*t + ccol;
        int row0 = bm + wm + mt*16 + crow;
        float o0 = gp[0] / (1.f + __expf(-gp[0])) * vp[0];
        float o1 = gp[1] / (1.f + __expf(-gp[1])) * vp[1];
        *(__half2*)&OUT[(size_t)row0 * stride + j0] = __floats2half2_rn(o0, o1);
        float o2 = gp[2] / (1.f + __expf(-gp[2])) * vp[2];
        float o3 = gp[3] / (1.f + __expf(-gp[3])) * vp[3];
        *(__half2*)&OUT[(size_t)(row0 + 8) * stride + j0] = __floats2half2_rn(o2, o3);
      }
    }
  } else {
#pragma unroll
    for (int mt = 0; mt < 2; mt++) {
#pragma unroll
      for (int n8 = 0; n8 < 8; n8++) {
        int col  = bn + wn + n8 * 8 + ccol;
        int row0 = bm + wm + mt * 16 + crow;
        const float* ap = acc[mt][n8];
        *(__half2*)&OUT[(size_t)row0 * N + col]       = __floats2half2_rn(ap[0], ap[1]);
        *(__half2*)&OUT[(size_t)(row0 + 8) * N + col] = __floats2half2_rn(ap[2], ap[3]);
      }
    }
  }
}

// ======================= windowed sigmoid attention =======================
// fp32 smem k/v tiles, 8 independent FMA chains; fp16->fp32 conversion only in fill.
#define AT_TOKS (128 + W_)   /* 160 */
#define AT_PAD  161
#define ATTN_SMEM (2 * 64 * AT_PAD * 4)   /* 82432 B */

__global__ __launch_bounds__(128) void attn_kernel(
    const __half* __restrict__ qkv, __half* __restrict__ msg) {
  extern __shared__ float smf[];
  float* ks = smf;
  float* vs = smf + 64 * AT_PAD;
  const int c = blockIdx.x, h = blockIdx.y, b = blockIdx.z;
  const int base = c * 128 - W_;
  const int tid = threadIdx.x;

  for (int i4 = tid; i4 < AT_TOKS * 32; i4 += 128) {
    int tok = i4 >> 5;
    int dq  = (i4 & 31) << 2;
    int tg  = base + tok;
    float4 v = make_float4(0.f, 0.f, 0.f, 0.f);
    if (tg >= 0)
      v = unpack4h(*(const uint2*)&qkv[(size_t)(b*T_ + tg)*(3*D_) + D_ + h*128 + dq]);
    float* dst = (dq < 64) ? (ks + dq*AT_PAD + tok) : (vs + (dq-64)*AT_PAD + tok);
    dst[0]        = v.x;
    dst[AT_PAD]   = v.y;
    dst[2*AT_PAD] = v.z;
    dst[3*AT_PAD] = v.w;
  }
  __syncthreads();

  const int tg = c * 128 + tid;
  const __half* qp = &qkv[(size_t)(b*T_ + tg)*(3*D_) + h*HD_];
  float qr[64];
#pragma unroll
  for (int i = 0; i < 16; i++) {
    float4 f = unpack4h(*(const uint2*)(qp + 4*i));
    qr[4*i]=f.x; qr[4*i+1]=f.y; qr[4*i+2]=f.z; qr[4*i+3]=f.w;
  }
  float acc[64];
#pragma unroll
  for (int d = 0; d < 64; d++) acc[d] = 0.f;

  const int jt = tid + W_;
#pragma unroll 4
  for (int w = 0; w < W_; w += 2) {
    const int j0 = jt - 1 - w;
    const int j1 = jt - 2 - w;
    float s0=0.f, s1=0.f, s2=0.f, s3=0.f;
    float u0=0.f, u1=0.f, u2=0.f, u3=0.f;
#pragma unroll
    for (int d = 0; d < 64; d += 4) {
      s0 += qr[d]   * ks[(d)  *AT_PAD + j0];
      s1 += qr[d+1] * ks[(d+1)*AT_PAD + j0];
      s2 += qr[d+2] * ks[(d+2)*AT_PAD + j0];
      s3 += qr[d+3] * ks[(d+3)*AT_PAD + j0];
      u0 += qr[d]   * ks[(d)  *AT_PAD + j1];
      u1 += qr[d+1] * ks[(d+1)*AT_PAD + j1];
      u2 += qr[d+2] * ks[(d+2)*AT_PAD + j1];
      u3 += qr[d+3] * ks[(d+3)*AT_PAD + j1];
    }
    float sA = (s0+s1) + (s2+s3);
    float sB = (u0+u1) + (u2+u3);
    float tau0 = 1.f / (1.f + __expf(-sA * 0.125f));
    float tau1 = 1.f / (1.f + __expf(-sB * 0.125f));
#pragma unroll
    for (int d = 0; d < 64; d++)
      acc[d] += tau0 * vs[d*AT_PAD + j0] + tau1 * vs[d*AT_PAD + j1];
  }

  size_t abase = (size_t)(b*T_ + tg) * D_;
  int off = h * HD_;
#pragma unroll
  for (int i = 0; i < 16; i++) {
    float4 v = make_float4(acc[4*i], acc[4*i+1], acc[4*i+2], acc[4*i+3]);
    *(uint2*)(msg + abase + off + 4*i) = pack4h(v);
  }
}

// ======================= LayerNorm =======================
// MODE 0: fp32 x -> fp16 out = LN(x)
// MODE 1: fp16 x,add -> fp16 out = LN(x+add) * (1 + amp*sin(t*freqs+phases))
// MODE 2: fp16 x,add -> fp32 out = LN(x+add)
template<int MODE>
__global__ __launch_bounds__(128) void ln_kernel(
    const void* __restrict__ xv, const __half* __restrict__ add,
    const float* __restrict__ g, const float* __restrict__ bb,
    const float* __restrict__ freqs, const float* __restrict__ phases,
    const float* __restrict__ amp, void* __restrict__ outv) {
  const int row = blockIdx.x;
  const int i = threadIdx.x;
  float4 f;
  if (MODE == 0) {
    f = ((const float4*)((const float*)xv + (size_t)row*D_))[i];
  } else {
    f = unpack4h(((const uint2*)((const __half*)xv + (size_t)row*D_))[i]);
    float4 a = unpack4h(((const uint2*)(add + (size_t)row*D_))[i]);
    f.x+=a.x; f.y+=a.y; f.z+=a.z; f.w+=a.w;
  }
  float s  = f.x + f.y + f.z + f.w;
  float ss = f.x*f.x + f.y*f.y + f.z*f.z + f.w*f.w;
#pragma unroll
  for (int o = 16; o > 0; o >>= 1) {
    s  += __shfl_xor_sync(0xffffffffu, s,  o);
    ss += __shfl_xor_sync(0xffffffffu, ss, o);
  }
  __shared__ float rs[4], rss[4];
  if ((i & 31) == 0) { rs[i>>5] = s; rss[i>>5] = ss; }
  __syncthreads();
  s  = rs[0]  + rs[1]  + rs[2]  + rs[3];
  ss = rss[0] + rss[1] + rss[2] + rss[3];
  const float mu   = s * (1.f/D_);
  const float var  = ss * (1.f/D_) - mu*mu;
  const float rstd = rsqrtf(var + 1e-5f);
  float4 gv = ((const float4*)g)[i];
  float4 bv = ((const float4*)bb)[i];
  float4 o;
  o.x = (f.x-mu)*rstd*gv.x + bv.x;
  o.y = (f.y-mu)*rstd*gv.y + bv.y;
  o.z = (f.z-mu)*rstd*gv.z + bv.z;
  o.w = (f.w-mu)*rstd*gv.w + bv.w;
  if (MODE == 1) {
    float t  = (float)(row & (T_-1));
    float av = amp[0];
    float4 fr = ((const float4*)freqs)[i];
    float4 ph = ((const float4*)phases)[i];
    o.x *= 1.f + av*sinf(t*fr.x + ph.x);
    o.y *= 1.f + av*sinf(t*fr.y + ph.y);
    o.z *= 1.f + av*sinf(t*fr.z + ph.z);
    o.w *= 1.f + av*sinf(t*fr.w + ph.w);
  }
  if (MODE == 2) {
    ((float4*)((float*)outv + (size_t)row*D_))[i] = o;
  } else {
    ((uint2*)((__half*)outv + (size_t)row*D_))[i] = pack4h(o);
  }
}

// ======================= launch =======================
extern "C" void kernel_launch(void* const* d_in, const int* in_sizes, int n_in,
                              void* d_out, int out_size) {
  const float* x      = (const float*)d_in[0];
  const float* pre_g  = (const float*)d_in[1];
  const float* pre_b  = (const float*)d_in[2];
  const float* wq     = (const float*)d_in[3];
  const float* wkv    = (const float*)d_in[4];
  const float* wo     = (const float*)d_in[5];
  const float* attn_g = (const float*)d_in[6];
  const float* attn_b = (const float*)d_in[7];
  const float* freqs  = (const float*)d_in[8];
  const float* phases = (const float*)d_in[9];
  const float* amp    = (const float*)d_in[10];
  const float* w_gate = (const float*)d_in[11];
  const float* w_val  = (const float*)d_in[12];
  const float* w_proj = (const float*)d_in[13];
  const float* ffn_g  = (const float*)d_in[14];
  const float* ffn_b  = (const float*)d_in[15];

  __half *h, *qkvh, *msg, *tmp, *y, *a3, *z, *b2;
  cudaGetSymbolAddress((void**)&h,    g_h);
  cudaGetSymbolAddress((void**)&qkvh, g_qkvh);
  cudaGetSymbolAddress((void**)&msg,  g_msg);
  cudaGetSymbolAddress((void**)&tmp,  g_tmp);
  cudaGetSymbolAddress((void**)&y,    g_y);
  cudaGetSymbolAddress((void**)&a3,   g_a3);
  cudaGetSymbolAddress((void**)&z,    g_z);
  cudaGetSymbolAddress((void**)&b2,   g_b2);

  cudaFuncSetAttribute(attn_kernel, cudaFuncAttributeMaxDynamicSharedMemorySize, ATTN_SMEM);
  cudaFuncSetAttribute(gemm_mma<1>, cudaFuncAttributeMaxDynamicSharedMemorySize, GEMM_DYN_SMEM);
  cudaFuncSetAttribute(gemm_mma<2>, cudaFuncAttributeMaxDynamicSharedMemorySize, GEMM_DYN_SMEM);

  // ---- fork side stream for all weight conversions (graph-capturable) ----
  cudaStream_t s2;
  cudaStreamCreateWithFlags(&s2, cudaStreamNonBlocking);
  cudaEvent_t ef, e1, e2, e3, e4;
  cudaEventCreateWithFlags(&ef, cudaEventDisableTiming);
  cudaEventCreateWithFlags(&e1, cudaEventDisableTiming);
  cudaEventCreateWithFlags(&e2, cudaEventDisableTiming);
  cudaEventCreateWithFlags(&e3, cudaEventDisableTiming);
  cudaEventCreateWithFlags(&e4, cudaEventDisableTiming);

  cudaEventRecord(ef, 0);
  cudaStreamWaitEvent(s2, ef, 0);
  split_bt_kernel<<<dim3(D_/32,   D_/32), dim3(32,32), 0, s2>>>(wq,  b2 + B2_QKV,          D_, D_);
  split_bt_kernel<<<dim3(2*D_/32, D_/32), dim3(32,32), 0, s2>>>(wkv, b2 + B2_QKV + D_*D_,  D_, 2*D_);
  cudaEventRecord(e1, s2);
  split_bt_kernel<<<dim3(D_/32, D_/32), dim3(32,32), 0, s2>>>(wo, b2 + B2_WO, D_, D_);
  cudaEventRecord(e2, s2);
  split_bt_ilv_kernel<<<dim3(HID_/32, D_/32), dim3(32,32), 0, s2>>>(w_gate, b2 + B2_GV, D_, HID_, 0);
  split_bt_ilv_kernel<<<dim3(HID_/32, D_/32), dim3(32,32), 0, s2>>>(w_val,  b2 + B2_GV, D_, HID_, 8);
  cudaEventRecord(e3, s2);
  split_bt_kernel<<<dim3(D_/32, HID_/32), dim3(32,32), 0, s2>>>(w_proj, b2 + B2_PROJ, HID_, D_);
  cudaEventRecord(e4, s2);

  // ---- main chain on default stream ----
  // 1) h = LN(x)
  ln_kernel<0><<<NTOK, 128>>>(x, nullptr, pre_g, pre_b, nullptr, nullptr, nullptr, h);

  // 2) qkv = h @ [wq | wkv]
  cudaStreamWaitEvent(0, e1, 0);
  gemm_mma<2><<<dim3(12, 64), 256, GEMM_DYN_SMEM>>>(h, b2 + B2_QKV, qkvh, 3*D_, D_);

  // 3) attention -> fp16 msg
  attn_kernel<<<dim3(T_/128, H_, B_), 128, ATTN_SMEM>>>(qkvh, msg);

  // 4) tmp = msg@wo ; y = LN(h+tmp)*(1+amp*sin)
  cudaStreamWaitEvent(0, e2, 0);
  gemm_mma<2><<<dim3(4, 64), 256, GEMM_DYN_SMEM>>>(msg, b2 + B2_WO, tmp, D_, D_);
  ln_kernel<1><<<NTOK, 128>>>(h, tmp, attn_g, attn_b, freqs, phases, amp, y);

  // 5) FFN: fused gv GEMM -> a3 ; z = a3 @ w_proj
  cudaStreamWaitEvent(0, e3, 0);
  gemm_mma<1><<<dim3(24, 64), 256, GEMM_DYN_SMEM>>>(y, b2 + B2_GV, a3, 2*HID_, D_);
  cudaStreamWaitEvent(0, e4, 0);
  gemm_mma<2><<<dim3(4, 64), 256, GEMM_DYN_SMEM>>>(a3, b2 + B2_PROJ, z, D_, HID_);

  // 6) out = LN(y + z)  (fp32 output)
  ln_kernel<2><<<NTOK, 128>>>(y, z, ffn_g, ffn_b, nullptr, nullptr, nullptr, d_out);
}